// round 10
// baseline (speedup 1.0000x reference)
#include <cuda_runtime.h>
#include <cstdint>

// GlobalMixer: y[b,h,o,g] = sum_i W[h,o,i] * x[b,h,i,g]
//   x: (B=512, H=512, SEQ=256) fp32, SEQ elem (i,g) at i*16+g
//   W: (H=512, 16, 16) fp32
//
// R10: R9 (82.0us) with 6 CTAs/SM (reg cap 85). R8/R9 established the
// mechanism: exposed CTA start/finish phases are the residual cost, and
// more independent phases per SM = higher sustained DRAM occupancy.
// R4 compiled this exact body to 80 regs under an 85 cap -> no spill risk.
// Everything else identical (g-quad, hoisted x-loads, unsplatted smem W,
// packed f32x2 FMA, streaming .cs).

#define HIDDEN 512
#define BATCH  512
#define B_PER_BLOCK 32
#define THREADS 128

__device__ __forceinline__ unsigned long long fma2(unsigned long long a,
                                                   unsigned long long b,
                                                   unsigned long long c) {
    unsigned long long d;
    asm("fma.rn.f32x2 %0, %1, %2, %3;" : "=l"(d) : "l"(a), "l"(b), "l"(c));
    return d;
}

__device__ __forceinline__ unsigned long long splat2(float w) {
    unsigned long long d;
    asm("mov.b64 %0, {%1, %1};" : "=l"(d) : "f"(w));
    return d;
}

__global__ __launch_bounds__(THREADS, 6)
void global_mixer_kernel(const float* __restrict__ x,
                         const float* __restrict__ W,
                         float* __restrict__ y) {
    __shared__ float ws[256];               // W[h] plain fp32, 1 KB

    const int h  = blockIdx.x;              // 0..511
    const int b0 = blockIdx.y * B_PER_BLOCK;
    const int t  = threadIdx.x;             // 0..127

    const int b_local = t >> 2;   // 0..31
    const int gq      = t & 3;    // g-quad -> g = 4*gq .. 4*gq+3

    const size_t base = ((size_t)(b0 + b_local) * HIDDEN + h) * 256 + gq * 4;
    const ulonglong2* __restrict__ xp =
        reinterpret_cast<const ulonglong2*>(x + base);
    ulonglong2* __restrict__ yp =
        reinterpret_cast<ulonglong2*>(y + base);

    // DRAM loads FIRST: overlap their latency with the W L2-load + STS + BAR
    ulonglong2 xv[16];
#pragma unroll
    for (int i = 0; i < 16; i++) xv[i] = __ldcs(xp + (size_t)i * 4);

    // W stage: 128 threads x 2 elements (L2-resident)
    ws[t]       = W[h * 256 + t];
    ws[t + 128] = W[h * 256 + t + 128];
    __syncthreads();

#pragma unroll
    for (int o = 0; o < 16; o++) {
        unsigned long long alo = 0ull, ahi = 0ull;
        const float4* __restrict__ wrow =
            reinterpret_cast<const float4*>(&ws[o * 16]);
#pragma unroll
        for (int i4 = 0; i4 < 4; i4++) {
            float4 w = wrow[i4];            // LDS.128: 4 distinct W values
            unsigned long long w0 = splat2(w.x);
            unsigned long long w1 = splat2(w.y);
            unsigned long long w2 = splat2(w.z);
            unsigned long long w3 = splat2(w.w);
            alo = fma2(xv[4 * i4 + 0].x, w0, alo);
            ahi = fma2(xv[4 * i4 + 0].y, w0, ahi);
            alo = fma2(xv[4 * i4 + 1].x, w1, alo);
            ahi = fma2(xv[4 * i4 + 1].y, w1, ahi);
            alo = fma2(xv[4 * i4 + 2].x, w2, alo);
            ahi = fma2(xv[4 * i4 + 2].y, w2, ahi);
            alo = fma2(xv[4 * i4 + 3].x, w3, alo);
            ahi = fma2(xv[4 * i4 + 3].y, w3, ahi);
        }
        ulonglong2 out; out.x = alo; out.y = ahi;
        __stcs(yp + (size_t)o * 4, out);    // STG.128 streaming, coalesced
    }
}

extern "C" void kernel_launch(void* const* d_in, const int* in_sizes, int n_in,
                              void* d_out, int out_size) {
    const float* x = (const float*)d_in[0];   // 512*512*256 fp32
    const float* W = (const float*)d_in[1];   // 512*16*16 fp32
    float* y = (float*)d_out;

    dim3 grid(HIDDEN, BATCH / B_PER_BLOCK);   // (512, 16)
    global_mixer_kernel<<<grid, THREADS>>>(x, W, y);
}

// round 11
// speedup vs baseline: 1.0012x; 1.0012x over previous
#include <cuda_runtime.h>
#include <cstdint>

// GlobalMixer: y[b,h,o,g] = sum_i W[h,o,i] * x[b,h,i,g]
//   x: (B=512, H=512, SEQ=256) fp32, SEQ elem (i,g) at i*16+g
//   W: (H=512, 16, 16) fp32
//
// R11: R9 (82.0us, best) with 64-thread CTAs: 8 independent CTA phases/SM
// (vs 4), natural 128 regs (R10 showed the 80-reg cap changes codegen for
// the worse), barrier couples only 2 warps, tail quantum halves.
// Per-thread code identical to R9: g-quad, hoisted front-batched x loads,
// unsplatted W in smem, packed f32x2 FMA, streaming .cs loads/stores.
//
// Ledger: occ (R4,R10), smoothness (R6), DRAM locality (R7) falsified;
// phase granularity + load hoist validated (R8, R9). This is the last
// notch on that curve; converged at the mixed-R/W HBM wall if neutral.

#define HIDDEN 512
#define BATCH  512
#define B_PER_BLOCK 16
#define THREADS 64

__device__ __forceinline__ unsigned long long fma2(unsigned long long a,
                                                   unsigned long long b,
                                                   unsigned long long c) {
    unsigned long long d;
    asm("fma.rn.f32x2 %0, %1, %2, %3;" : "=l"(d) : "l"(a), "l"(b), "l"(c));
    return d;
}

__device__ __forceinline__ unsigned long long splat2(float w) {
    unsigned long long d;
    asm("mov.b64 %0, {%1, %1};" : "=l"(d) : "f"(w));
    return d;
}

__global__ __launch_bounds__(THREADS, 8)
void global_mixer_kernel(const float* __restrict__ x,
                         const float* __restrict__ W,
                         float* __restrict__ y) {
    __shared__ float ws[256];               // W[h] plain fp32, 1 KB

    const int h  = blockIdx.x;              // 0..511
    const int b0 = blockIdx.y * B_PER_BLOCK;
    const int t  = threadIdx.x;             // 0..63

    const int b_local = t >> 2;   // 0..15
    const int gq      = t & 3;    // g-quad -> g = 4*gq .. 4*gq+3

    const size_t base = ((size_t)(b0 + b_local) * HIDDEN + h) * 256 + gq * 4;
    const ulonglong2* __restrict__ xp =
        reinterpret_cast<const ulonglong2*>(x + base);
    ulonglong2* __restrict__ yp =
        reinterpret_cast<ulonglong2*>(y + base);

    // DRAM loads FIRST: overlap their latency with the W L2-load + STS + BAR
    ulonglong2 xv[16];
#pragma unroll
    for (int i = 0; i < 16; i++) xv[i] = __ldcs(xp + (size_t)i * 4);

    // W stage: 64 threads x 4 elements (L2-resident, coalesced)
#pragma unroll
    for (int k = 0; k < 4; k++)
        ws[t + 64 * k] = W[h * 256 + t + 64 * k];
    __syncthreads();

#pragma unroll
    for (int o = 0; o < 16; o++) {
        unsigned long long alo = 0ull, ahi = 0ull;
        const float4* __restrict__ wrow =
            reinterpret_cast<const float4*>(&ws[o * 16]);
#pragma unroll
        for (int i4 = 0; i4 < 4; i4++) {
            float4 w = wrow[i4];            // LDS.128: 4 distinct W values
            unsigned long long w0 = splat2(w.x);
            unsigned long long w1 = splat2(w.y);
            unsigned long long w2 = splat2(w.z);
            unsigned long long w3 = splat2(w.w);
            alo = fma2(xv[4 * i4 + 0].x, w0, alo);
            ahi = fma2(xv[4 * i4 + 0].y, w0, ahi);
            alo = fma2(xv[4 * i4 + 1].x, w1, alo);
            ahi = fma2(xv[4 * i4 + 1].y, w1, ahi);
            alo = fma2(xv[4 * i4 + 2].x, w2, alo);
            ahi = fma2(xv[4 * i4 + 2].y, w2, ahi);
            alo = fma2(xv[4 * i4 + 3].x, w3, alo);
            ahi = fma2(xv[4 * i4 + 3].y, w3, ahi);
        }
        ulonglong2 out; out.x = alo; out.y = ahi;
        __stcs(yp + (size_t)o * 4, out);    // STG.128 streaming, coalesced
    }
}

extern "C" void kernel_launch(void* const* d_in, const int* in_sizes, int n_in,
                              void* d_out, int out_size) {
    const float* x = (const float*)d_in[0];   // 512*512*256 fp32
    const float* W = (const float*)d_in[1];   // 512*16*16 fp32
    float* y = (float*)d_out;

    dim3 grid(HIDDEN, BATCH / B_PER_BLOCK);   // (512, 32)
    global_mixer_kernel<<<grid, THREADS>>>(x, W, y);
}